// round 2
// baseline (speedup 1.0000x reference)
#include <cuda_runtime.h>
#include <cuda_bf16.h>
#include <cooperative_groups.h>
#include <math.h>

namespace cg = cooperative_groups;

// ---------------- Problem constants ----------------
#define BB     64          // batch
#define TT     2048        // time steps
#define DD     256         // input dim
#define HH     256         // hidden dim
#define G4     1024        // 4*H
#define OO     128         // output dim

// ---------------- Device-global scratch (static: no allocs allowed) ----------------
__device__ float g_Wx[DD * G4];          // permuted input weights  [k][g']   1 MB
__device__ float g_Wh[HH * G4];          // permuted hidden weights [k][g']   1 MB
__device__ float g_b4[G4];               // permuted bias
__device__ float g_xproj[(size_t)TT * BB * G4];   // [t][b][g']  512 MB
__device__ float g_hfinal[BB * HH];

// =====================================================================
// K0: permute weights: g' = j*4 + G  (G: 0=f,1=i,2=c,3=o)
// W_G is (H, D+H) row-major: W_G[j][k] input part k<256, hidden part k>=256
// =====================================================================
__global__ void k0_permute(const float* __restrict__ Wf, const float* __restrict__ Wi,
                           const float* __restrict__ Wc, const float* __restrict__ Wo,
                           const float* __restrict__ bf, const float* __restrict__ bi,
                           const float* __restrict__ bc, const float* __restrict__ bo)
{
    int k = blockIdx.x;        // 0..255
    int g = threadIdx.x;       // 0..1023
    int j = g >> 2;
    int G = g & 3;
    const float* W = (G == 0) ? Wf : (G == 1) ? Wi : (G == 2) ? Wc : Wo;
    g_Wx[k * G4 + g] = W[j * (DD + HH) + k];
    g_Wh[k * G4 + g] = W[j * (DD + HH) + DD + k];
    if (k == 0) {
        const float* bbp = (G == 0) ? bf : (G == 1) ? bi : (G == 2) ? bc : bo;
        g_b4[g] = bbp[j];
    }
}

// =====================================================================
// K1: x_proj[t][b][g'] = sum_d inputs[b][t][d] * Wx[d][g'] + b4[g']
// Grid: (8 g-chunks of 128, 2048 t). 256 threads. Tile: As[64][64], Bs[32][128].
// Each thread: 8(b) x 4(g) register tile.
// =====================================================================
__global__ void __launch_bounds__(256) k1_xproj(const float* __restrict__ inputs)
{
    __shared__ __align__(16) float As[64][64];
    __shared__ __align__(16) float Bs[32][128];

    int t   = blockIdx.y;
    int gc  = blockIdx.x * 128;
    int tid = threadIdx.x;
    int tx  = tid & 31;        // g sub-block
    int ty  = tid >> 5;        // b sub-block

    float acc[8][4];
#pragma unroll
    for (int i = 0; i < 8; i++)
#pragma unroll
        for (int j = 0; j < 4; j++) acc[i][j] = 0.f;

    for (int kc = 0; kc < 4; kc++) {            // 4 chunks of 64 K
        __syncthreads();
        // load As[64][64] : inputs[b][t][kc*64 + d]
#pragma unroll
        for (int u = 0; u < 4; u++) {
            int lin = tid + 256 * u;            // float4 index 0..1023
            int b   = lin >> 4;                 // 16 float4 per row
            int d4  = lin & 15;
            *(float4*)&As[b][4 * d4] =
                *(const float4*)&inputs[((size_t)b * TT + t) * DD + kc * 64 + 4 * d4];
        }
#pragma unroll
        for (int h = 0; h < 2; h++) {           // 2 sub-chunks of 32 K
            __syncthreads();
#pragma unroll
            for (int u = 0; u < 4; u++) {
                int lin = tid + 256 * u;        // float4 index
                int kk  = lin >> 5;             // 32 float4 per row of 128
                int c4  = lin & 31;
                *(float4*)&Bs[kk][4 * c4] =
                    *(const float4*)&g_Wx[(size_t)(kc * 64 + h * 32 + kk) * G4 + gc + 4 * c4];
            }
            __syncthreads();
#pragma unroll
            for (int kk = 0; kk < 32; kk++) {
                float4 bv = *(float4*)&Bs[kk][tx * 4];
#pragma unroll
                for (int i = 0; i < 8; i++) {
                    float a = As[ty * 8 + i][h * 32 + kk];
                    acc[i][0] = fmaf(a, bv.x, acc[i][0]);
                    acc[i][1] = fmaf(a, bv.y, acc[i][1]);
                    acc[i][2] = fmaf(a, bv.z, acc[i][2]);
                    acc[i][3] = fmaf(a, bv.w, acc[i][3]);
                }
            }
        }
    }
    float4 bias = *(const float4*)&g_b4[gc + tx * 4];
#pragma unroll
    for (int i = 0; i < 8; i++) {
        float4 r;
        r.x = acc[i][0] + bias.x;
        r.y = acc[i][1] + bias.y;
        r.z = acc[i][2] + bias.z;
        r.w = acc[i][3] + bias.w;
        *(float4*)&g_xproj[((size_t)t * BB + ty * 8 + i) * G4 + gc + tx * 4] = r;
    }
}

// =====================================================================
// K2: recurrent scan. 16 clusters x 8 CTAs. Cluster c owns batches [4c,4c+4).
// CTA rank s owns gate cols [128s,128s+128) == h indices [32s,32s+32) x 4 gates.
// Wh slice in registers (128 fp32/thread: thread=(col 0..127, khalf 0..1)).
// Per step: partial GEMM -> smem reduce (+x_proj) -> sigmoid/tanh (c in regs)
//           -> slice to smem -> cluster.sync -> DSMEM all-gather of h.
// =====================================================================
__global__ void __cluster_dims__(8, 1, 1) __launch_bounds__(256, 1)
k2_recurrent()
{
    cg::cluster_group cluster = cg::this_cluster();

    __shared__ __align__(16) float h_full[2][4][HH];   // 8 KB
    __shared__ __align__(16) float part[2][4][128];    // 4 KB
    __shared__ __align__(16) float xbuf[2][4][128];    // 4 KB
    __shared__ __align__(16) float slice[2][4][32];    // 1 KB

    const int tid   = threadIdx.x;
    const unsigned s = cluster.block_rank();           // 0..7
    const int cid   = blockIdx.x >> 3;                 // cluster id 0..15
    const int bbase = cid * 4;
    const int gbase = (int)s * 128;
    const int col   = tid & 127;
    const int kh    = tid >> 7;                        // K half 0/1

    // ---- weights to registers: W[r] = Wh[kh*128 + r][gbase+col]
    float4 Wv[32];
#pragma unroll
    for (int r4 = 0; r4 < 32; r4++) {
        Wv[r4].x = g_Wh[(size_t)(kh * 128 + 4 * r4 + 0) * G4 + gbase + col];
        Wv[r4].y = g_Wh[(size_t)(kh * 128 + 4 * r4 + 1) * G4 + gbase + col];
        Wv[r4].z = g_Wh[(size_t)(kh * 128 + 4 * r4 + 2) * G4 + gbase + col];
        Wv[r4].w = g_Wh[(size_t)(kh * 128 + 4 * r4 + 3) * G4 + gbase + col];
    }

    // ---- init h=0, preload x(t=0)
    for (int q = tid; q < 4 * HH; q += 256) ((float*)h_full[0])[q] = 0.f;
    if (tid < 128) {
        int b = tid >> 5, q = tid & 31;
        *(float4*)&xbuf[0][b][4 * q] =
            *(const float4*)&g_xproj[((size_t)0 * BB + bbase + b) * G4 + gbase + 4 * q];
    }
    float c_state = 0.f;
    const int rb = tid >> 5;   // reducer batch  (tid<128)
    const int rj = tid & 31;   // reducer h-local
    __syncthreads();

    for (int t = 0; t < TT; t++) {
        const int cur = t & 1, nxt = cur ^ 1;

        // prefetch x(t+1) into registers
        float4 xv = make_float4(0.f, 0.f, 0.f, 0.f);
        const bool pf = (tid < 128) && (t + 1 < TT);
        if (pf) {
            int b = tid >> 5, q = tid & 31;
            xv = *(const float4*)&g_xproj[((size_t)(t + 1) * BB + bbase + b) * G4 + gbase + 4 * q];
        }

        // ---- partial GEMM: acc[b] = sum_r W[r] * h[b][kh*128+r]
        float a0 = 0.f, a1 = 0.f, a2 = 0.f, a3 = 0.f;
#pragma unroll
        for (int r4 = 0; r4 < 32; r4++) {
            float4 w  = Wv[r4];
            float4 h0 = *(const float4*)&h_full[cur][0][kh * 128 + 4 * r4];
            float4 h1 = *(const float4*)&h_full[cur][1][kh * 128 + 4 * r4];
            float4 h2 = *(const float4*)&h_full[cur][2][kh * 128 + 4 * r4];
            float4 h3 = *(const float4*)&h_full[cur][3][kh * 128 + 4 * r4];
            a0 = fmaf(w.x, h0.x, a0); a0 = fmaf(w.y, h0.y, a0);
            a0 = fmaf(w.z, h0.z, a0); a0 = fmaf(w.w, h0.w, a0);
            a1 = fmaf(w.x, h1.x, a1); a1 = fmaf(w.y, h1.y, a1);
            a1 = fmaf(w.z, h1.z, a1); a1 = fmaf(w.w, h1.w, a1);
            a2 = fmaf(w.x, h2.x, a2); a2 = fmaf(w.y, h2.y, a2);
            a2 = fmaf(w.z, h2.z, a2); a2 = fmaf(w.w, h2.w, a2);
            a3 = fmaf(w.x, h3.x, a3); a3 = fmaf(w.y, h3.y, a3);
            a3 = fmaf(w.z, h3.z, a3); a3 = fmaf(w.w, h3.w, a3);
        }
        part[kh][0][col] = a0;
        part[kh][1][col] = a1;
        part[kh][2][col] = a2;
        part[kh][3][col] = a3;
        if (pf) {
            int b = tid >> 5, q = tid & 31;
            *(float4*)&xbuf[nxt][b][4 * q] = xv;
        }
        __syncthreads();

        // ---- reduce + activations (128 threads: one per (b, h_local))
        if (tid < 128) {
            float4 p0 = *(const float4*)&part[0][rb][4 * rj];
            float4 p1 = *(const float4*)&part[1][rb][4 * rj];
            float4 xq = *(const float4*)&xbuf[cur][rb][4 * rj];
            float gf = p0.x + p1.x + xq.x;
            float gi = p0.y + p1.y + xq.y;
            float gcv = p0.z + p1.z + xq.z;
            float go = p0.w + p1.w + xq.w;
            float f  = 1.f / (1.f + expf(-gf));
            float ii = 1.f / (1.f + expf(-gi));
            float ch = tanhf(gcv);
            float o  = 1.f / (1.f + expf(-go));
            c_state  = fmaf(f, c_state, ii * ch);
            float hn = o * tanhf(c_state);
            slice[nxt][rb][rj] = hn;
            h_full[nxt][rb][(int)s * 32 + rj] = hn;
            if (t == TT - 1) g_hfinal[(bbase + rb) * HH + (int)s * 32 + rj] = hn;
        }

        cluster.sync();

        // ---- DSMEM all-gather of peer h slices into h_full[nxt]
        {
            unsigned rr = (unsigned)(tid >> 5);     // source rank 0..7
            int idx = tid & 31;
            int b   = idx >> 3;
            int seg = idx & 7;                       // float4 segment 0..7
            if (rr != s) {
                const float4* peer = (const float4*)cluster.map_shared_rank(
                    (void*)&slice[nxt][b][4 * seg], rr);
                float4 v = *peer;
                *(float4*)&h_full[nxt][b][(int)rr * 32 + 4 * seg] = v;
            }
        }
        __syncthreads();
    }
}

// =====================================================================
// K3: out[b][o] = sum_k hT[b][k] * W_out[o][k] + b_out[o]
// =====================================================================
__global__ void k3_output(const float* __restrict__ W_out, const float* __restrict__ b_out,
                          float* __restrict__ out)
{
    __shared__ __align__(16) float hs[HH];
    int b = blockIdx.x;
    int o = threadIdx.x;                 // 128 threads
    hs[o]       = g_hfinal[b * HH + o];
    hs[o + 128] = g_hfinal[b * HH + 128 + o];
    __syncthreads();
    float acc = b_out[o];
#pragma unroll
    for (int k4 = 0; k4 < HH / 4; k4++) {
        float4 w = *(const float4*)&W_out[(size_t)o * HH + 4 * k4];
        float4 h = *(const float4*)&hs[4 * k4];
        acc = fmaf(w.x, h.x, acc);
        acc = fmaf(w.y, h.y, acc);
        acc = fmaf(w.z, h.z, acc);
        acc = fmaf(w.w, h.w, acc);
    }
    out[b * OO + o] = acc;
}

// =====================================================================
// kernel_launch
// inputs order: inputs, W_f, b_f, W_i, b_i, W_c, b_c, W_o, b_o, W_out, b_out
// =====================================================================
extern "C" void kernel_launch(void* const* d_in, const int* in_sizes, int n_in,
                              void* d_out, int out_size)
{
    const float* inputs = (const float*)d_in[0];
    const float* Wf = (const float*)d_in[1];
    const float* bf = (const float*)d_in[2];
    const float* Wi = (const float*)d_in[3];
    const float* bi = (const float*)d_in[4];
    const float* Wc = (const float*)d_in[5];
    const float* bc = (const float*)d_in[6];
    const float* Wo = (const float*)d_in[7];
    const float* bo = (const float*)d_in[8];
    const float* W_out = (const float*)d_in[9];
    const float* b_out = (const float*)d_in[10];
    float* out = (float*)d_out;

    k0_permute<<<DD, G4>>>(Wf, Wi, Wc, Wo, bf, bi, bc, bo);
    dim3 g1(G4 / 128, TT);
    k1_xproj<<<g1, 256>>>(inputs);
    k2_recurrent<<<128, 256>>>();
    k3_output<<<BB, OO>>>(W_out, b_out, out);
}

// round 3
// speedup vs baseline: 1.2088x; 1.2088x over previous
#include <cuda_runtime.h>
#include <cuda_bf16.h>
#include <cooperative_groups.h>
#include <math.h>
#include <stdint.h>

namespace cg = cooperative_groups;

// ---------------- Problem constants ----------------
#define BB     64          // batch
#define TT     2048        // time steps
#define DD     256         // input dim
#define HH     256         // hidden dim
#define G4     1024        // 4*H
#define OO     128         // output dim

// ---------------- Device-global scratch ----------------
__device__ float g_Wx[DD * G4];
__device__ float g_Wh[HH * G4];
__device__ float g_b4[G4];
__device__ float g_xproj[(size_t)TT * BB * G4];   // [t][b][g']
__device__ float g_hfinal[BB * HH];

// ---------------- packed f32x2 helpers ----------------
__device__ __forceinline__ unsigned long long ffma2(unsigned long long a,
                                                    unsigned long long b,
                                                    unsigned long long c) {
    unsigned long long d;
    asm("fma.rn.f32x2 %0, %1, %2, %3;" : "=l"(d) : "l"(a), "l"(b), "l"(c));
    return d;
}
__device__ __forceinline__ unsigned long long pack2(float lo, float hi) {
    unsigned long long d;
    asm("mov.b64 %0, {%1, %2};" : "=l"(d) : "f"(lo), "f"(hi));
    return d;
}
__device__ __forceinline__ float2 unpack2(unsigned long long v) {
    float2 r;
    asm("mov.b64 {%0, %1}, %2;" : "=f"(r.x), "=f"(r.y) : "l"(v));
    return r;
}

// ---------------- fast activations ----------------
__device__ __forceinline__ float fsig(float x) {
    float e = __expf(-x);
    return __fdividef(1.f, 1.f + e);
}
__device__ __forceinline__ float ftanh(float x) {
    x = fminf(fmaxf(x, -15.f), 15.f);
    float e = __expf(-2.f * x);
    return __fdividef(1.f - e, 1.f + e);
}

// ---------------- smem / cluster / mbarrier helpers ----------------
__device__ __forceinline__ uint32_t smem_u32(const void* p) {
    return (uint32_t)__cvta_generic_to_shared(p);
}
__device__ __forceinline__ uint32_t mapa_u32(uint32_t laddr, uint32_t rank) {
    uint32_t r;
    asm("mapa.shared::cluster.u32 %0, %1, %2;" : "=r"(r) : "r"(laddr), "r"(rank));
    return r;
}
__device__ __forceinline__ void st_async64(uint32_t raddr, unsigned long long v,
                                           uint32_t rbar) {
    asm volatile(
        "st.async.shared::cluster.mbarrier::complete_tx::bytes.b64 [%0], %1, [%2];"
        :: "r"(raddr), "l"(v), "r"(rbar) : "memory");
}
__device__ __forceinline__ void mbar_init(uint32_t addr, uint32_t count) {
    asm volatile("mbarrier.init.shared.b64 [%0], %1;" :: "r"(addr), "r"(count) : "memory");
}
__device__ __forceinline__ void mbar_expect_tx(uint32_t addr, uint32_t bytes) {
    asm volatile("mbarrier.arrive.expect_tx.shared.b64 _, [%0], %1;"
                 :: "r"(addr), "r"(bytes) : "memory");
}
__device__ __forceinline__ void mbar_wait_parity(uint32_t addr, uint32_t parity) {
    uint32_t done;
    asm volatile(
        "{\n\t.reg .pred p;\n\t"
        "mbarrier.try_wait.parity.acquire.cta.shared::cta.b64 p, [%1], %2;\n\t"
        "selp.b32 %0, 1, 0, p;\n\t}"
        : "=r"(done) : "r"(addr), "r"(parity) : "memory");
    if (!done) {
        asm volatile(
            "{\n\t.reg .pred P1;\n\t"
            "WL_%=:\n\t"
            "mbarrier.try_wait.parity.acquire.cta.shared::cta.b64 P1, [%0], %1, 0x989680;\n\t"
            "@P1 bra.uni WD_%=;\n\t"
            "bra.uni WL_%=;\n\t"
            "WD_%=:\n\t}"
            :: "r"(addr), "r"(parity) : "memory");
    }
}

// =====================================================================
// K0: permute weights: g' = j*4 + G  (G: 0=f,1=i,2=c,3=o)
// =====================================================================
__global__ void k0_permute(const float* __restrict__ Wf, const float* __restrict__ Wi,
                           const float* __restrict__ Wc, const float* __restrict__ Wo,
                           const float* __restrict__ bf, const float* __restrict__ bi,
                           const float* __restrict__ bc, const float* __restrict__ bo)
{
    int k = blockIdx.x;
    int g = threadIdx.x;
    int j = g >> 2;
    int G = g & 3;
    const float* W = (G == 0) ? Wf : (G == 1) ? Wi : (G == 2) ? Wc : Wo;
    g_Wx[k * G4 + g] = W[j * (DD + HH) + k];
    g_Wh[k * G4 + g] = W[j * (DD + HH) + DD + k];
    if (k == 0) {
        const float* bbp = (G == 0) ? bf : (G == 1) ? bi : (G == 2) ? bc : bo;
        g_b4[g] = bbp[j];
    }
}

// =====================================================================
// K1: x_proj[t][b][g'] = sum_d inputs[b][t][d] * Wx[d][g'] + b4[g']
// f32x2-packed over the g dimension (column pairs).
// =====================================================================
__global__ void __launch_bounds__(256) k1_xproj(const float* __restrict__ inputs)
{
    __shared__ __align__(16) float As[64][64];
    __shared__ __align__(16) float Bs[32][128];

    int t   = blockIdx.y;
    int gc  = blockIdx.x * 128;
    int tid = threadIdx.x;
    int tx  = tid & 31;
    int ty  = tid >> 5;

    unsigned long long acc2[8][2];
#pragma unroll
    for (int i = 0; i < 8; i++) { acc2[i][0] = 0ULL; acc2[i][1] = 0ULL; }

    for (int kc = 0; kc < 4; kc++) {
        __syncthreads();
#pragma unroll
        for (int u = 0; u < 4; u++) {
            int lin = tid + 256 * u;
            int b   = lin >> 4;
            int d4  = lin & 15;
            *(float4*)&As[b][4 * d4] =
                *(const float4*)&inputs[((size_t)b * TT + t) * DD + kc * 64 + 4 * d4];
        }
#pragma unroll
        for (int h = 0; h < 2; h++) {
            __syncthreads();
#pragma unroll
            for (int u = 0; u < 4; u++) {
                int lin = tid + 256 * u;
                int kk  = lin >> 5;
                int c4  = lin & 31;
                *(float4*)&Bs[kk][4 * c4] =
                    *(const float4*)&g_Wx[(size_t)(kc * 64 + h * 32 + kk) * G4 + gc + 4 * c4];
            }
            __syncthreads();
#pragma unroll
            for (int kk = 0; kk < 32; kk++) {
                ulonglong2 bv2 = *(const ulonglong2*)&Bs[kk][tx * 4];
#pragma unroll
                for (int i = 0; i < 8; i++) {
                    float a = As[ty * 8 + i][h * 32 + kk];
                    unsigned long long a2 = pack2(a, a);
                    acc2[i][0] = ffma2(a2, bv2.x, acc2[i][0]);
                    acc2[i][1] = ffma2(a2, bv2.y, acc2[i][1]);
                }
            }
        }
    }
    float4 bias = *(const float4*)&g_b4[gc + tx * 4];
#pragma unroll
    for (int i = 0; i < 8; i++) {
        float2 c01 = unpack2(acc2[i][0]);
        float2 c23 = unpack2(acc2[i][1]);
        float4 r;
        r.x = c01.x + bias.x;
        r.y = c01.y + bias.y;
        r.z = c23.x + bias.z;
        r.w = c23.y + bias.w;
        *(float4*)&g_xproj[((size_t)t * BB + ty * 8 + i) * G4 + gc + tx * 4] = r;
    }
}

// =====================================================================
// K2: recurrent scan. 16 clusters x 8 CTAs, 1 wave (128 CTAs).
// f32x2-packed GEMM (Wh slice in 128 regs/thread), fast activations,
// st.async push-exchange on a transaction mbarrier (no cluster.sync
// per step: the expect_tx(4096B) completion certifies both data-ready
// and all-peers-done-reading).
// =====================================================================
__global__ void __cluster_dims__(8, 1, 1) __launch_bounds__(256, 1)
k2_recurrent()
{
    cg::cluster_group cluster = cg::this_cluster();

    __shared__ __align__(16) float h_full[2][4][HH];   // 8 KB (t-parity double buffer)
    __shared__ __align__(16) float part[2][4][128];    // 4 KB ([khalf][b][col])
    __shared__ __align__(16) float xbuf[2][4][128];    // 4 KB (t-parity double buffer)
    __shared__ __align__(16) float slice[4][32];       // 512 B staging
    __shared__ __align__(8)  unsigned long long mbar;  // transaction barrier

    const int tid    = threadIdx.x;
    const unsigned s = cluster.block_rank();           // 0..7
    const int cid    = blockIdx.x >> 3;
    const int bbase  = cid * 4;
    const int gbase  = (int)s * 128;
    const int col    = tid & 127;
    const int kh     = tid >> 7;                       // K half 0/1
    const int K0     = kh * 128;
    const int lane   = tid & 31;
    const unsigned w = (unsigned)(tid >> 5);           // warp index == dest rank

    // ---- packed weights: W2[r2] = (Wh[K0+2r2][g], Wh[K0+2r2+1][g])
    unsigned long long W2[64];
    {
        const int g = gbase + col;
#pragma unroll
        for (int r2 = 0; r2 < 64; r2++) {
            float w0 = g_Wh[(size_t)(K0 + 2 * r2)     * G4 + g];
            float w1 = g_Wh[(size_t)(K0 + 2 * r2 + 1) * G4 + g];
            W2[r2] = pack2(w0, w1);
        }
    }

    // ---- push-address precompute (each warp pushes the slice to rank w)
    const int b0 = lane >> 4;
    const int j0 = (lane & 15) * 2;
    const uint32_t l_bar = smem_u32(&mbar);
    const uint32_t r_bar = mapa_u32(l_bar, w);
    uint32_t r_h[2][2];
#pragma unroll
    for (int p = 0; p < 2; p++) {
        r_h[p][0] = mapa_u32(smem_u32(&h_full[p][b0    ][(int)s * 32 + j0]), w);
        r_h[p][1] = mapa_u32(smem_u32(&h_full[p][b0 + 2][(int)s * 32 + j0]), w);
    }

    // ---- init
    if (tid == 0) mbar_init(l_bar, 1);
    for (int q = tid; q < 4 * HH; q += 256) ((float*)h_full[0])[q] = 0.f;
    if (tid < 128) {
        int b = tid >> 5, q = tid & 31;
        *(float4*)&xbuf[0][b][4 * q] =
            *(const float4*)&g_xproj[((size_t)0 * BB + bbase + b) * G4 + gbase + 4 * q];
    }
    float c_state = 0.f;
    const int rb = tid >> 5;   // reducer batch (tid<128)
    const int rj = tid & 31;   // reducer h-local
    __syncthreads();
    cluster.sync();            // barriers + h init visible cluster-wide

    for (int t = 0; t < TT; t++) {
        const int cur = t & 1, nxt = cur ^ 1;

        // prefetch x(t+1)
        float4 xv = make_float4(0.f, 0.f, 0.f, 0.f);
        const bool pf = (tid < 128) && (t + 1 < TT);
        if (pf) {
            int b = tid >> 5, q = tid & 31;
            xv = *(const float4*)&g_xproj[((size_t)(t + 1) * BB + bbase + b) * G4 + gbase + 4 * q];
        }

        // ---- partial GEMM (f32x2): acc[b] += W[k] * h[b][K0+k]
        unsigned long long ac0 = 0ULL, ac1 = 0ULL, ac2 = 0ULL, ac3 = 0ULL;
#pragma unroll
        for (int it = 0; it < 32; it++) {
            const float* hb = &h_full[cur][0][K0 + it * 4];
            ulonglong2 h0 = *(const ulonglong2*)(hb);
            ulonglong2 h1 = *(const ulonglong2*)(hb + HH);
            ulonglong2 h2 = *(const ulonglong2*)(hb + 2 * HH);
            ulonglong2 h3 = *(const ulonglong2*)(hb + 3 * HH);
            ac0 = ffma2(W2[2 * it],     h0.x, ac0);
            ac0 = ffma2(W2[2 * it + 1], h0.y, ac0);
            ac1 = ffma2(W2[2 * it],     h1.x, ac1);
            ac1 = ffma2(W2[2 * it + 1], h1.y, ac1);
            ac2 = ffma2(W2[2 * it],     h2.x, ac2);
            ac2 = ffma2(W2[2 * it + 1], h2.y, ac2);
            ac3 = ffma2(W2[2 * it],     h3.x, ac3);
            ac3 = ffma2(W2[2 * it + 1], h3.y, ac3);
        }
        {
            float2 p0 = unpack2(ac0), p1 = unpack2(ac1);
            float2 p2 = unpack2(ac2), p3 = unpack2(ac3);
            part[kh][0][col] = p0.x + p0.y;
            part[kh][1][col] = p1.x + p1.y;
            part[kh][2][col] = p2.x + p2.y;
            part[kh][3][col] = p3.x + p3.y;
        }
        if (pf) {
            int b = tid >> 5, q = tid & 31;
            *(float4*)&xbuf[nxt][b][4 * q] = xv;
        }
        __syncthreads();

        // ---- reduce + activations (128 threads: one per (b, h_local))
        if (tid < 128) {
            float4 p0 = *(const float4*)&part[0][rb][4 * rj];
            float4 p1 = *(const float4*)&part[1][rb][4 * rj];
            float4 xq = *(const float4*)&xbuf[cur][rb][4 * rj];
            float gf  = p0.x + p1.x + xq.x;
            float gi  = p0.y + p1.y + xq.y;
            float gcv = p0.z + p1.z + xq.z;
            float go  = p0.w + p1.w + xq.w;
            float f   = fsig(gf);
            float ii  = fsig(gi);
            float ch  = ftanh(gcv);
            float o   = fsig(go);
            c_state   = fmaf(f, c_state, ii * ch);
            float hn  = o * ftanh(c_state);
            slice[rb][rj] = hn;
            if (t == TT - 1) g_hfinal[(bbase + rb) * HH + (int)s * 32 + rj] = hn;
        }
        __syncthreads();

        // ---- push-exchange: warp w sends the full 512B slice to rank w
        if (t < TT - 1) {
            const float* sf = &slice[0][0];
            unsigned long long v0 = *(const unsigned long long*)(sf + 2 * lane);
            unsigned long long v1 = *(const unsigned long long*)(sf + 2 * (lane + 32));
            st_async64(r_h[nxt][0], v0, r_bar);
            st_async64(r_h[nxt][1], v1, r_bar);
            if (tid == 0) mbar_expect_tx(l_bar, 8 * 512);   // 8 ranks x 512B
            mbar_wait_parity(l_bar, (uint32_t)(t & 1));
        }
    }
}

// =====================================================================
// K3: out[b][o] = sum_k hT[b][k] * W_out[o][k] + b_out[o]
// =====================================================================
__global__ void k3_output(const float* __restrict__ W_out, const float* __restrict__ b_out,
                          float* __restrict__ out)
{
    __shared__ __align__(16) float hs[HH];
    int b = blockIdx.x;
    int o = threadIdx.x;
    hs[o]       = g_hfinal[b * HH + o];
    hs[o + 128] = g_hfinal[b * HH + 128 + o];
    __syncthreads();
    float acc = b_out[o];
#pragma unroll
    for (int k4 = 0; k4 < HH / 4; k4++) {
        float4 wv = *(const float4*)&W_out[(size_t)o * HH + 4 * k4];
        float4 h  = *(const float4*)&hs[4 * k4];
        acc = fmaf(wv.x, h.x, acc);
        acc = fmaf(wv.y, h.y, acc);
        acc = fmaf(wv.z, h.z, acc);
        acc = fmaf(wv.w, h.w, acc);
    }
    out[b * OO + o] = acc;
}

// =====================================================================
// kernel_launch
// =====================================================================
extern "C" void kernel_launch(void* const* d_in, const int* in_sizes, int n_in,
                              void* d_out, int out_size)
{
    const float* inputs = (const float*)d_in[0];
    const float* Wf = (const float*)d_in[1];
    const float* bf = (const float*)d_in[2];
    const float* Wi = (const float*)d_in[3];
    const float* bi = (const float*)d_in[4];
    const float* Wc = (const float*)d_in[5];
    const float* bc = (const float*)d_in[6];
    const float* Wo = (const float*)d_in[7];
    const float* bo = (const float*)d_in[8];
    const float* W_out = (const float*)d_in[9];
    const float* b_out = (const float*)d_in[10];
    float* out = (float*)d_out;

    k0_permute<<<DD, G4>>>(Wf, Wi, Wc, Wo, bf, bi, bc, bo);
    dim3 g1(G4 / 128, TT);
    k1_xproj<<<g1, 256>>>(inputs);
    k2_recurrent<<<128, 256>>>();
    k3_output<<<BB, OO>>>(W_out, b_out, out);
}